// round 11
// baseline (speedup 1.0000x reference)
#include <cuda_runtime.h>
#include <math.h>

#define NN 50000
#define EE 800000
#define ET 850000          // EE + NN self loops
#define FH 128             // H * C
#define CC 64
#define NEG 0.2f
#define EPSN 1e-5f

// ---------------- scratch (static device, no allocation) ----------------
__device__ __align__(16) float g_xl[NN * FH];
__device__ __align__(16) float g_xr[NN * FH];
__device__ __align__(16) float g_xpre[NN * CC];
__device__ float g_cs[3 * CC];
__device__ float g_css[3 * CC];
__device__ int   g_deg[NN];
__device__ int   g_rowptr[NN + 1];
__device__ int   g_cursor[NN];
__device__ int   g_csrc[ET];

__device__ __forceinline__ float lrelu(float v) {
    return fmaxf(v, NEG * v);          // 2 ops: FMUL + FMNMX
}

// packed f32x2 helpers (Blackwell FFMA2 path, PTX-only)
typedef unsigned long long u64t;
__device__ __forceinline__ void fma2(u64t& d, u64t a, u64t b) {
    asm("fma.rn.f32x2 %0, %1, %2, %3;" : "=l"(d) : "l"(a), "l"(b), "l"(d));
}

// ================= CSR build =============================================
__global__ void k_histo(const int* __restrict__ ei) {
    int e = blockIdx.x * blockDim.x + threadIdx.x;
    if (e >= ET) return;
    int d = (e < EE) ? __ldg(ei + EE + e) : (e - EE);
    atomicAdd(&g_deg[d], 1);
}

__global__ void k_scan() {
    __shared__ int wsum[32];
    __shared__ int carry;
    int tid = threadIdx.x, lane = tid & 31, wid = tid >> 5;
    if (tid == 0) carry = 0;
    __syncthreads();
    for (int base = 0; base < NN; base += 1024) {
        int i = base + tid;
        int v = (i < NN) ? g_deg[i] : 0;
        int s = v;
#pragma unroll
        for (int off = 1; off < 32; off <<= 1) {
            int t = __shfl_up_sync(0xffffffffu, s, off);
            if (lane >= off) s += t;
        }
        if (lane == 31) wsum[wid] = s;
        __syncthreads();
        if (wid == 0) {
            int w = wsum[lane];
#pragma unroll
            for (int off = 1; off < 32; off <<= 1) {
                int t = __shfl_up_sync(0xffffffffu, w, off);
                if (lane >= off) w += t;
            }
            wsum[lane] = w;
        }
        __syncthreads();
        int boff = carry + (wid ? wsum[wid - 1] : 0);
        if (i < NN) {
            int ex = boff + s - v;
            g_rowptr[i] = ex;
            g_cursor[i] = ex;
        }
        __syncthreads();
        if (tid == 0) carry += wsum[31];
        __syncthreads();
    }
    if (tid == 0) g_rowptr[NN] = carry;
}

__global__ void k_scatter(const int* __restrict__ ei) {
    int e = blockIdx.x * blockDim.x + threadIdx.x;
    if (e >= ET) return;
    int s, d;
    if (e < EE) { s = __ldg(ei + e); d = __ldg(ei + EE + e); }
    else        { s = e - EE; d = s; }
    int pos = atomicAdd(&g_cursor[d], 1);
    g_csrc[pos] = s;
}

// ================= per-layer kernels =====================================

// xl = x@Wl, xr = x@Wr (f32x2 FMA), prev-layer norm+relu folded into staging.
__global__ void k_gemm(const float* __restrict__ xin,
                       const float* __restrict__ Wl,
                       const float* __restrict__ Wr, int din,
                       const float* __restrict__ gw,
                       const float* __restrict__ gb,
                       const float* __restrict__ gm,
                       const float* __restrict__ cs,
                       const float* __restrict__ css) {
    __shared__ float2 sx[32][CC];
    int lane = threadIdx.x;
    int tid  = threadIdx.y * 32 + lane;
    int nodeBase = blockIdx.x * 32;

    if (xin) {                         // layer 1: raw external input
        for (int idx = tid; idx < 32 * din; idx += 128) {
            int n = idx / din, k = idx % din;
            float v = (nodeBase + n < NN)
                    ? __ldg(xin + (size_t)(nodeBase + n) * din + k) : 0.f;
            sx[n][k] = make_float2(v, v);
        }
    } else {                           // din == 64: norm+relu fold
        const float invN = 1.f / (float)NN;
        for (int idx = tid; idx < 32 * CC; idx += 128) {
            int n = idx >> 6, c = idx & 63;
            float v = 0.f;
            if (nodeBase + n < NN) {
                float raw = g_xpre[(size_t)(nodeBase + n) * CC + c];
                float mu  = __ldg(cs + c)  * invN;
                float msq = __ldg(css + c) * invN;
                float ms  = __ldg(gm + c);
                float var = msq - 2.f * ms * mu * mu + ms * ms * mu * mu;
                float o = raw - ms * mu;
                v = fmaxf(__ldg(gw + c) * o * rsqrtf(var + EPSN) + __ldg(gb + c), 0.f);
            }
            sx[n][c] = make_float2(v, v);
        }
    }
    __syncthreads();

    int nrow = threadIdx.y * 8;
    u64t al[8][2], ar[8][2];
#pragma unroll
    for (int nn = 0; nn < 8; nn++) {
        al[nn][0] = al[nn][1] = 0ull;
        ar[nn][0] = ar[nn][1] = 0ull;
    }
    for (int k = 0; k < din; k++) {
        ulonglong2 wl = *(const ulonglong2*)(Wl + k * FH + lane * 4);
        ulonglong2 wr = *(const ulonglong2*)(Wr + k * FH + lane * 4);
#pragma unroll
        for (int nn = 0; nn < 8; nn++) {
            u64t xx = *(const u64t*)&sx[nrow + nn][k];
            fma2(al[nn][0], xx, wl.x);
            fma2(al[nn][1], xx, wl.y);
            fma2(ar[nn][0], xx, wr.x);
            fma2(ar[nn][1], xx, wr.y);
        }
    }
#pragma unroll
    for (int nn = 0; nn < 8; nn++) {
        int node = nodeBase + nrow + nn;
        if (node < NN) {
            ulonglong2 vl; vl.x = al[nn][0]; vl.y = al[nn][1];
            ulonglong2 vr; vr.x = ar[nn][0]; vr.y = ar[nn][1];
            *(ulonglong2*)(g_xl + (size_t)node * FH + lane * 4) = vl;
            *(ulonglong2*)(g_xr + (size_t)node * FH + lane * 4) = vr;
        }
    }
}

// Fused attention v4: warp per node, FOUR parallel edge-streams per warp
// (grp = lane>>3), each stream 8 lanes x 16 floats. 2-shfl logit reduce,
// 2-level decoupled prefetch (MLP=4 rows), NaN-safe end merge, warp-local
// head-mean finalize via shfl. Block smem only for column stats.
__global__ void k_attn(const float* __restrict__ att,
                       const float* __restrict__ b,
                       float* __restrict__ cs,
                       float* __restrict__ css) {
    __shared__ float ss[CC], sq[CC];
    const unsigned F = 0xffffffffu;
    int tid  = threadIdx.x;
    int warp = tid >> 5, lane = tid & 31;
    int node = blockIdx.x * 8 + warp;              // NN % 8 == 0

    if (tid < CC) { ss[tid] = 0.f; sq[tid] = 0.f; }
    __syncthreads();

    int sub  = lane & 7, grp = lane >> 3;
    int head = sub >> 2;
    int cbase = head * CC + (sub & 3) * 16;        // this lane's 16 columns

    const float4* xrp = (const float4*)(g_xr + (size_t)node * FH + cbase);
    float4 xr0 = xrp[0], xr1 = xrp[1], xr2 = xrp[2], xr3 = xrp[3];
    const float4* wp = (const float4*)(att + cbase);
    float4 w0 = wp[0], w1 = wp[1], w2 = wp[2], w3 = wp[3];

    int i0 = g_rowptr[node], i1 = g_rowptr[node + 1];
    int i  = i0 + grp;
    int nIter = (i1 - i0 + 3) >> 2;

    int sp = __ldg(g_csrc + min(i, i1 - 1));
    const float4* rp = (const float4*)(g_xl + (size_t)sp * FH + cbase);
    float4 r0 = rp[0], r1 = rp[1], r2 = rp[2], r3 = rp[3];
    int snext = __ldg(g_csrc + min(i + 4, i1 - 1));

    float m = -INFINITY, z = 0.f;
    float4 a0 = {0,0,0,0}, a1 = {0,0,0,0}, a2 = {0,0,0,0}, a3 = {0,0,0,0};

    for (int it = 0; it < nIter; it++) {
        float4 c0 = r0, c1 = r1, c2 = r2, c3 = r3;
        bool act = i < i1;
        i += 4;
        // row prefetch for iter+1 (idx already resident), idx for iter+2
        const float4* np = (const float4*)(g_xl + (size_t)snext * FH + cbase);
        r0 = np[0]; r1 = np[1]; r2 = np[2]; r3 = np[3];
        snext = __ldg(g_csrc + min(i + 4, i1 - 1));

        float p;
        p  = lrelu(c0.x + xr0.x) * w0.x;
        p += lrelu(c0.y + xr0.y) * w0.y;
        p += lrelu(c0.z + xr0.z) * w0.z;
        p += lrelu(c0.w + xr0.w) * w0.w;
        p += lrelu(c1.x + xr1.x) * w1.x;
        p += lrelu(c1.y + xr1.y) * w1.y;
        p += lrelu(c1.z + xr1.z) * w1.z;
        p += lrelu(c1.w + xr1.w) * w1.w;
        p += lrelu(c2.x + xr2.x) * w2.x;
        p += lrelu(c2.y + xr2.y) * w2.y;
        p += lrelu(c2.z + xr2.z) * w2.z;
        p += lrelu(c2.w + xr2.w) * w2.w;
        p += lrelu(c3.x + xr3.x) * w3.x;
        p += lrelu(c3.y + xr3.y) * w3.y;
        p += lrelu(c3.z + xr3.z) * w3.z;
        p += lrelu(c3.w + xr3.w) * w3.w;
        p += __shfl_xor_sync(F, p, 1);   // reduce within 4-lane head half
        p += __shfl_xor_sync(F, p, 2);

        if (act) {
            float mn = fmaxf(m, p);
            float sc = __expf(m - mn);   // first edge: exp(-inf)=0
            float e  = __expf(p - mn);
            z = z * sc + e;
            a0.x = fmaf(a0.x, sc, e * c0.x);  a0.y = fmaf(a0.y, sc, e * c0.y);
            a0.z = fmaf(a0.z, sc, e * c0.z);  a0.w = fmaf(a0.w, sc, e * c0.w);
            a1.x = fmaf(a1.x, sc, e * c1.x);  a1.y = fmaf(a1.y, sc, e * c1.y);
            a1.z = fmaf(a1.z, sc, e * c1.z);  a1.w = fmaf(a1.w, sc, e * c1.w);
            a2.x = fmaf(a2.x, sc, e * c2.x);  a2.y = fmaf(a2.y, sc, e * c2.y);
            a2.z = fmaf(a2.z, sc, e * c2.z);  a2.w = fmaf(a2.w, sc, e * c2.w);
            a3.x = fmaf(a3.x, sc, e * c3.x);  a3.y = fmaf(a3.y, sc, e * c3.y);
            a3.z = fmaf(a3.z, sc, e * c3.z);  a3.w = fmaf(a3.w, sc, e * c3.w);
            m = mn;
        }
    }

    // merge 4 streams (xor 8, then 16); equality-guarded scales avoid NaN
#pragma unroll
    for (int off = 8; off <= 16; off <<= 1) {
        float mo = __shfl_xor_sync(F, m, off);
        float zo = __shfl_xor_sync(F, z, off);
        float4 b0, b1, b2, b3;
        b0.x = __shfl_xor_sync(F, a0.x, off); b0.y = __shfl_xor_sync(F, a0.y, off);
        b0.z = __shfl_xor_sync(F, a0.z, off); b0.w = __shfl_xor_sync(F, a0.w, off);
        b1.x = __shfl_xor_sync(F, a1.x, off); b1.y = __shfl_xor_sync(F, a1.y, off);
        b1.z = __shfl_xor_sync(F, a1.z, off); b1.w = __shfl_xor_sync(F, a1.w, off);
        b2.x = __shfl_xor_sync(F, a2.x, off); b2.y = __shfl_xor_sync(F, a2.y, off);
        b2.z = __shfl_xor_sync(F, a2.z, off); b2.w = __shfl_xor_sync(F, a2.w, off);
        b3.x = __shfl_xor_sync(F, a3.x, off); b3.y = __shfl_xor_sync(F, a3.y, off);
        b3.z = __shfl_xor_sync(F, a3.z, off); b3.w = __shfl_xor_sync(F, a3.w, off);
        float mn  = fmaxf(m, mo);
        float sc0 = (m  >= mn) ? 1.f : __expf(m  - mn);
        float sc1 = (mo >= mn) ? 1.f : __expf(mo - mn);
        z = z * sc0 + zo * sc1;
        a0.x = a0.x*sc0 + b0.x*sc1;  a0.y = a0.y*sc0 + b0.y*sc1;
        a0.z = a0.z*sc0 + b0.z*sc1;  a0.w = a0.w*sc0 + b0.w*sc1;
        a1.x = a1.x*sc0 + b1.x*sc1;  a1.y = a1.y*sc0 + b1.y*sc1;
        a1.z = a1.z*sc0 + b1.z*sc1;  a1.w = a1.w*sc0 + b1.w*sc1;
        a2.x = a2.x*sc0 + b2.x*sc1;  a2.y = a2.y*sc0 + b2.y*sc1;
        a2.z = a2.z*sc0 + b2.z*sc1;  a2.w = a2.w*sc0 + b2.w*sc1;
        a3.x = a3.x*sc0 + b3.x*sc1;  a3.y = a3.y*sc0 + b3.y*sc1;
        a3.z = a3.z*sc0 + b3.z*sc1;  a3.w = a3.w*sc0 + b3.w*sc1;
        m = mn;
    }

    // normalize, head-mean via shfl_xor 4 (partner = other head, same cols)
    float iz = 1.f / z;
    float y[16];
    y[0]=a0.x*iz;  y[1]=a0.y*iz;  y[2]=a0.z*iz;  y[3]=a0.w*iz;
    y[4]=a1.x*iz;  y[5]=a1.y*iz;  y[6]=a1.z*iz;  y[7]=a1.w*iz;
    y[8]=a2.x*iz;  y[9]=a2.y*iz;  y[10]=a2.z*iz; y[11]=a2.w*iz;
    y[12]=a3.x*iz; y[13]=a3.y*iz; y[14]=a3.z*iz; y[15]=a3.w*iz;
#pragma unroll
    for (int q = 0; q < 16; q++)
        y[q] = 0.5f * (y[q] + __shfl_xor_sync(F, y[q], 4));

    if (grp == 0 && head == 0) {           // lanes 0-3: 16 cols each
        int col0 = (sub & 3) * 16;
        const float4* bp = (const float4*)(b + col0);
        float4 o[4];
#pragma unroll
        for (int q = 0; q < 4; q++) {
            float4 bb = bp[q];
            o[q].x = y[q*4+0] + bb.x;  o[q].y = y[q*4+1] + bb.y;
            o[q].z = y[q*4+2] + bb.z;  o[q].w = y[q*4+3] + bb.w;
        }
        float4* op = (float4*)(g_xpre + (size_t)node * CC + col0);
#pragma unroll
        for (int q = 0; q < 4; q++) op[q] = o[q];
#pragma unroll
        for (int q = 0; q < 16; q++) {
            float v = ((const float*)o)[q];
            atomicAdd(&ss[col0 + q], v);
            atomicAdd(&sq[col0 + q], v * v);
        }
    }
    __syncthreads();
    if (tid < CC) {
        atomicAdd(&cs[tid],  ss[tid]);
        atomicAdd(&css[tid], sq[tid]);
    }
}

// final graph norm + relu (layer 3 only)
__global__ void k_norm(const float* __restrict__ gw,
                       const float* __restrict__ gb,
                       const float* __restrict__ gm,
                       const float* __restrict__ cs,
                       const float* __restrict__ css,
                       float* __restrict__ out) {
    int idx = blockIdx.x * blockDim.x + threadIdx.x;
    int c = idx & 63;
    float inv = 1.f / (float)NN;
    float mu  = __ldg(cs + c)  * inv;
    float msq = __ldg(css + c) * inv;
    float ms  = __ldg(gm + c);
    float var = msq - 2.f * ms * mu * mu + ms * ms * mu * mu;
    float o = g_xpre[idx] - ms * mu;
    float y = __ldg(gw + c) * o * rsqrtf(var + EPSN) + __ldg(gb + c);
    out[idx] = fmaxf(y, 0.f);
}

// ---------------- launch ----------------
extern "C" void kernel_launch(void* const* d_in, const int* in_sizes, int n_in,
                              void* d_out, int out_size) {
    const float* x  = (const float*)d_in[0];
    const int*   ei = (const int*)d_in[1];
    float* out = (float*)d_out;

    float *cs0, *css0; int* dDeg;
    cudaGetSymbolAddress((void**)&cs0,  g_cs);
    cudaGetSymbolAddress((void**)&css0, g_css);
    cudaGetSymbolAddress((void**)&dDeg, g_deg);

    static cudaStream_t s2 = nullptr;
    static cudaEvent_t evA = nullptr, evB = nullptr;
    if (!s2) {
        cudaStreamCreateWithFlags(&s2, cudaStreamNonBlocking);
        cudaEventCreateWithFlags(&evA, cudaEventDisableTiming);
        cudaEventCreateWithFlags(&evB, cudaEventDisableTiming);
    }

    const int edgeBlocks = (ET + 255) / 256;       // 3321
    const int gemmBlocks = (NN + 31) / 32;         // 1563
    const int attnBlocks = NN / 8;                 // 6250
    const int normBlocks = (NN * CC) / 256;        // 12500

    // fork: CSR build on s2, overlapped with layer-1 GEMM
    cudaEventRecord(evA, 0);
    cudaStreamWaitEvent(s2, evA, 0);
    cudaMemsetAsync(dDeg, 0, NN * sizeof(int), s2);
    k_histo<<<edgeBlocks, 256, 0, s2>>>(ei);
    k_scan<<<1, 1024, 0, s2>>>();
    k_scatter<<<edgeBlocks, 256, 0, s2>>>(ei);
    cudaEventRecord(evB, s2);

    cudaMemsetAsync(cs0,  0, 3 * CC * sizeof(float), 0);
    cudaMemsetAsync(css0, 0, 3 * CC * sizeof(float), 0);

    const float* xin = x;
    int din = 3;
    const float *pgw = nullptr, *pgb = nullptr, *pgm = nullptr;
    for (int l = 0; l < 3; l++) {
        int base = 2 + 7 * l;
        const float* Wl  = (const float*)d_in[base + 0];
        const float* Wr  = (const float*)d_in[base + 1];
        const float* att = (const float*)d_in[base + 2];
        const float* b   = (const float*)d_in[base + 3];

        float* csP  = cs0  + (l > 0 ? (l - 1) * CC : 0);
        float* cssP = css0 + (l > 0 ? (l - 1) * CC : 0);
        k_gemm<<<gemmBlocks, dim3(32, 4)>>>(xin, Wl, Wr, din,
                                            pgw, pgb, pgm, csP, cssP);
        if (l == 0) cudaStreamWaitEvent(0, evB, 0);
        k_attn<<<attnBlocks, 256>>>(att, b, cs0 + l * CC, css0 + l * CC);

        pgw = (const float*)d_in[base + 4];
        pgb = (const float*)d_in[base + 5];
        pgm = (const float*)d_in[base + 6];
        xin = nullptr;
        din = CC;
    }
    k_norm<<<normBlocks, 256>>>(pgw, pgb, pgm,
                                cs0 + 2 * CC, css0 + 2 * CC, out);
}

// round 13
// speedup vs baseline: 1.8096x; 1.8096x over previous
#include <cuda_runtime.h>
#include <math.h>

#define NN 50000
#define EE 800000
#define ET 850000          // EE + NN self loops
#define FH 128             // H * C
#define CC 64
#define NEG 0.2f
#define EPSN 1e-5f

// ---------------- scratch (static device, no allocation) ----------------
__device__ __align__(16) float g_xl[NN * FH];
__device__ __align__(16) float g_xr[NN * FH];
__device__ __align__(16) float g_xpre[NN * CC];
__device__ float g_cs[3 * CC];
__device__ float g_css[3 * CC];
__device__ int   g_deg[NN];
__device__ int   g_rowptr[NN + 1];
__device__ int   g_cursor[NN];
__device__ int   g_csrc[ET];

__device__ __forceinline__ float lrelu(float v) {
    return fmaxf(v, NEG * v);          // 2 ops: FMUL + FMNMX
}

// packed f32x2 helpers (Blackwell FFMA2 path, PTX-only)
typedef unsigned long long u64t;
__device__ __forceinline__ void fma2(u64t& d, u64t a, u64t b) {
    asm("fma.rn.f32x2 %0, %1, %2, %3;" : "=l"(d) : "l"(a), "l"(b), "l"(d));
}

// ================= CSR build =============================================
__global__ void k_histo(const int* __restrict__ ei) {
    int e = blockIdx.x * blockDim.x + threadIdx.x;
    if (e >= ET) return;
    int d = (e < EE) ? __ldg(ei + EE + e) : (e - EE);
    atomicAdd(&g_deg[d], 1);
}

__global__ void k_scan() {
    __shared__ int wsum[32];
    __shared__ int carry;
    int tid = threadIdx.x, lane = tid & 31, wid = tid >> 5;
    if (tid == 0) carry = 0;
    __syncthreads();
    for (int base = 0; base < NN; base += 1024) {
        int i = base + tid;
        int v = (i < NN) ? g_deg[i] : 0;
        int s = v;
#pragma unroll
        for (int off = 1; off < 32; off <<= 1) {
            int t = __shfl_up_sync(0xffffffffu, s, off);
            if (lane >= off) s += t;
        }
        if (lane == 31) wsum[wid] = s;
        __syncthreads();
        if (wid == 0) {
            int w = wsum[lane];
#pragma unroll
            for (int off = 1; off < 32; off <<= 1) {
                int t = __shfl_up_sync(0xffffffffu, w, off);
                if (lane >= off) w += t;
            }
            wsum[lane] = w;
        }
        __syncthreads();
        int boff = carry + (wid ? wsum[wid - 1] : 0);
        if (i < NN) {
            int ex = boff + s - v;
            g_rowptr[i] = ex;
            g_cursor[i] = ex;
        }
        __syncthreads();
        if (tid == 0) carry += wsum[31];
        __syncthreads();
    }
    if (tid == 0) g_rowptr[NN] = carry;
}

__global__ void k_scatter(const int* __restrict__ ei) {
    int e = blockIdx.x * blockDim.x + threadIdx.x;
    if (e >= ET) return;
    int s, d;
    if (e < EE) { s = __ldg(ei + e); d = __ldg(ei + EE + e); }
    else        { s = e - EE; d = s; }
    int pos = atomicAdd(&g_cursor[d], 1);
    g_csrc[pos] = s;
}

// ================= per-layer kernels =====================================

// xl = x@Wl, xr = x@Wr (f32x2 FMA), prev-layer norm+relu folded into staging.
__global__ void k_gemm(const float* __restrict__ xin,
                       const float* __restrict__ Wl,
                       const float* __restrict__ Wr, int din,
                       const float* __restrict__ gw,
                       const float* __restrict__ gb,
                       const float* __restrict__ gm,
                       const float* __restrict__ cs,
                       const float* __restrict__ css) {
    __shared__ float2 sx[32][CC];
    int lane = threadIdx.x;
    int tid  = threadIdx.y * 32 + lane;
    int nodeBase = blockIdx.x * 32;

    if (xin) {                         // layer 1: raw external input
        for (int idx = tid; idx < 32 * din; idx += 128) {
            int n = idx / din, k = idx % din;
            float v = (nodeBase + n < NN)
                    ? __ldg(xin + (size_t)(nodeBase + n) * din + k) : 0.f;
            sx[n][k] = make_float2(v, v);
        }
    } else {                           // din == 64: norm+relu fold
        const float invN = 1.f / (float)NN;
        for (int idx = tid; idx < 32 * CC; idx += 128) {
            int n = idx >> 6, c = idx & 63;
            float v = 0.f;
            if (nodeBase + n < NN) {
                float raw = g_xpre[(size_t)(nodeBase + n) * CC + c];
                float mu  = __ldg(cs + c)  * invN;
                float msq = __ldg(css + c) * invN;
                float ms  = __ldg(gm + c);
                float var = msq - 2.f * ms * mu * mu + ms * ms * mu * mu;
                float o = raw - ms * mu;
                v = fmaxf(__ldg(gw + c) * o * rsqrtf(var + EPSN) + __ldg(gb + c), 0.f);
            }
            sx[n][c] = make_float2(v, v);
        }
    }
    __syncthreads();

    int nrow = threadIdx.y * 8;
    u64t al[8][2], ar[8][2];
#pragma unroll
    for (int nn = 0; nn < 8; nn++) {
        al[nn][0] = al[nn][1] = 0ull;
        ar[nn][0] = ar[nn][1] = 0ull;
    }
    for (int k = 0; k < din; k++) {
        ulonglong2 wl = *(const ulonglong2*)(Wl + k * FH + lane * 4);
        ulonglong2 wr = *(const ulonglong2*)(Wr + k * FH + lane * 4);
#pragma unroll
        for (int nn = 0; nn < 8; nn++) {
            u64t xx = *(const u64t*)&sx[nrow + nn][k];
            fma2(al[nn][0], xx, wl.x);
            fma2(al[nn][1], xx, wl.y);
            fma2(ar[nn][0], xx, wr.x);
            fma2(ar[nn][1], xx, wr.y);
        }
    }
#pragma unroll
    for (int nn = 0; nn < 8; nn++) {
        int node = nodeBase + nrow + nn;
        if (node < NN) {
            ulonglong2 vl; vl.x = al[nn][0]; vl.y = al[nn][1];
            ulonglong2 vr; vr.x = ar[nn][0]; vr.y = ar[nn][1];
            *(ulonglong2*)(g_xl + (size_t)node * FH + lane * 4) = vl;
            *(ulonglong2*)(g_xr + (size_t)node * FH + lane * 4) = vr;
        }
    }
}

// Fused attention v3.1: warp per node, TWO parallel edge-streams per warp
// (lanes 0-15 even CSR slots, 16-31 odd). Within a half: 8 lanes/head,
// 8 floats/lane. Decoupled 2-level prefetch: row loads use an index fetched
// one iteration earlier; index fetch runs two pairs ahead. Independent
// online softmax per half, merged at the end (shfl_xor 16). Fuses
// head-mean + bias + column stats.
__global__ void __launch_bounds__(256, 4)
k_attn(const float* __restrict__ att,
       const float* __restrict__ b,
       float* __restrict__ cs,
       float* __restrict__ css) {
    __shared__ float sh[8][FH];
    __shared__ float ss[CC], sq[CC];
    const unsigned F = 0xffffffffu;
    int tid  = threadIdx.x;
    int warp = tid >> 5, lane = tid & 31;
    int node = blockIdx.x * 8 + warp;              // NN % 8 == 0

    if (tid < CC) { ss[tid] = 0.f; sq[tid] = 0.f; }

    int h16 = lane >> 4;                 // edge-stream (parity)
    int sub = lane & 15;
    int cbase = (sub >> 3) * CC + (sub & 7) * 8;   // head*64 + q*8

    float4 xr_a = *(const float4*)(g_xr + (size_t)node * FH + cbase);
    float4 xr_b = *(const float4*)(g_xr + (size_t)node * FH + cbase + 4);
    float4 w_a  = *(const float4*)(att + cbase);
    float4 w_b  = *(const float4*)(att + cbase + 4);

    int i0 = g_rowptr[node], i1 = g_rowptr[node + 1];
    int nIter = (i1 - i0 + 1) >> 1;

    float m = -INFINITY, z = 0.f;
    float4 A = make_float4(0.f, 0.f, 0.f, 0.f);
    float4 B = make_float4(0.f, 0.f, 0.f, 0.f);

    int idx = i0 + h16;
    // prologue: current row resident, next index resident
    int sc0 = __ldg(g_csrc + min(idx, i1 - 1));
    float4 xA = *(const float4*)(g_xl + (size_t)sc0 * FH + cbase);
    float4 xB = *(const float4*)(g_xl + (size_t)sc0 * FH + cbase + 4);
    int sNext = __ldg(g_csrc + min(idx + 2, i1 - 1));

    for (int it = 0; it < nIter; it++) {
        bool act = idx < i1;
        float4 x0 = xA, x1 = xB;
        idx += 2;
        // row prefetch for next iter uses already-resident sNext
        xA = *(const float4*)(g_xl + (size_t)sNext * FH + cbase);
        xB = *(const float4*)(g_xl + (size_t)sNext * FH + cbase + 4);
        // index prefetch two pairs ahead
        sNext = __ldg(g_csrc + min(idx + 2, i1 - 1));

        float p;
        p = lrelu(x0.x + xr_a.x) * w_a.x;
        p = fmaf(lrelu(x0.y + xr_a.y), w_a.y, p);
        p = fmaf(lrelu(x0.z + xr_a.z), w_a.z, p);
        p = fmaf(lrelu(x0.w + xr_a.w), w_a.w, p);
        p = fmaf(lrelu(x1.x + xr_b.x), w_b.x, p);
        p = fmaf(lrelu(x1.y + xr_b.y), w_b.y, p);
        p = fmaf(lrelu(x1.z + xr_b.z), w_b.z, p);
        p = fmaf(lrelu(x1.w + xr_b.w), w_b.w, p);
        p += __shfl_xor_sync(F, p, 4);   // reduce within 8-lane head group
        p += __shfl_xor_sync(F, p, 2);
        p += __shfl_xor_sync(F, p, 1);

        if (act) {
            float mn = fmaxf(m, p);
            float c  = __expf(m - mn);   // first edge: exp(-inf)=0
            float e  = __expf(p - mn);
            z = fmaf(z, c, e);
            A.x = fmaf(A.x, c, e * x0.x);  A.y = fmaf(A.y, c, e * x0.y);
            A.z = fmaf(A.z, c, e * x0.z);  A.w = fmaf(A.w, c, e * x0.w);
            B.x = fmaf(B.x, c, e * x1.x);  B.y = fmaf(B.y, c, e * x1.y);
            B.z = fmaf(B.z, c, e * x1.z);  B.w = fmaf(B.w, c, e * x1.w);
            m = mn;
        }
    }

    // merge the two halves' softmax states (per head group)
    float mo = __shfl_xor_sync(F, m, 16);
    float zo = __shfl_xor_sync(F, z, 16);
    float4 Ao, Bo;
    Ao.x = __shfl_xor_sync(F, A.x, 16);  Ao.y = __shfl_xor_sync(F, A.y, 16);
    Ao.z = __shfl_xor_sync(F, A.z, 16);  Ao.w = __shfl_xor_sync(F, A.w, 16);
    Bo.x = __shfl_xor_sync(F, B.x, 16);  Bo.y = __shfl_xor_sync(F, B.y, 16);
    Bo.z = __shfl_xor_sync(F, B.z, 16);  Bo.w = __shfl_xor_sync(F, B.w, 16);

    float mn = fmaxf(m, mo);
    float c0 = (m  >= mn) ? 1.f : __expf(m  - mn);
    float c1 = (mo >= mn) ? 1.f : __expf(mo - mn);
    float iz = 1.f / (z * c0 + zo * c1);

    if (h16 == 0) {
        sh[warp][cbase + 0] = (A.x * c0 + Ao.x * c1) * iz;
        sh[warp][cbase + 1] = (A.y * c0 + Ao.y * c1) * iz;
        sh[warp][cbase + 2] = (A.z * c0 + Ao.z * c1) * iz;
        sh[warp][cbase + 3] = (A.w * c0 + Ao.w * c1) * iz;
        sh[warp][cbase + 4] = (B.x * c0 + Bo.x * c1) * iz;
        sh[warp][cbase + 5] = (B.y * c0 + Bo.y * c1) * iz;
        sh[warp][cbase + 6] = (B.z * c0 + Bo.z * c1) * iz;
        sh[warp][cbase + 7] = (B.w * c0 + Bo.w * c1) * iz;
    }
    __syncthreads();

#pragma unroll
    for (int rep = 0; rep < 2; rep++) {
        int idx2 = rep * 256 + tid;
        int nl = idx2 >> 6, c = idx2 & 63;
        float v = 0.5f * (sh[nl][c] + sh[nl][CC + c]) + __ldg(b + c);
        g_xpre[(size_t)(blockIdx.x * 8 + nl) * CC + c] = v;
        atomicAdd(&ss[c], v);
        atomicAdd(&sq[c], v * v);
    }
    __syncthreads();
    if (tid < CC) {
        atomicAdd(&cs[tid],  ss[tid]);
        atomicAdd(&css[tid], sq[tid]);
    }
}

// final graph norm + relu (layer 3 only)
__global__ void k_norm(const float* __restrict__ gw,
                       const float* __restrict__ gb,
                       const float* __restrict__ gm,
                       const float* __restrict__ cs,
                       const float* __restrict__ css,
                       float* __restrict__ out) {
    int idx = blockIdx.x * blockDim.x + threadIdx.x;
    int c = idx & 63;
    float inv = 1.f / (float)NN;
    float mu  = __ldg(cs + c)  * inv;
    float msq = __ldg(css + c) * inv;
    float ms  = __ldg(gm + c);
    float var = msq - 2.f * ms * mu * mu + ms * ms * mu * mu;
    float o = g_xpre[idx] - ms * mu;
    float y = __ldg(gw + c) * o * rsqrtf(var + EPSN) + __ldg(gb + c);
    out[idx] = fmaxf(y, 0.f);
}

// ---------------- launch ----------------
extern "C" void kernel_launch(void* const* d_in, const int* in_sizes, int n_in,
                              void* d_out, int out_size) {
    const float* x  = (const float*)d_in[0];
    const int*   ei = (const int*)d_in[1];
    float* out = (float*)d_out;

    float *cs0, *css0; int* dDeg;
    cudaGetSymbolAddress((void**)&cs0,  g_cs);
    cudaGetSymbolAddress((void**)&css0, g_css);
    cudaGetSymbolAddress((void**)&dDeg, g_deg);

    static cudaStream_t s2 = nullptr;
    static cudaEvent_t evA = nullptr, evB = nullptr;
    if (!s2) {
        cudaStreamCreateWithFlags(&s2, cudaStreamNonBlocking);
        cudaEventCreateWithFlags(&evA, cudaEventDisableTiming);
        cudaEventCreateWithFlags(&evB, cudaEventDisableTiming);
    }

    const int edgeBlocks = (ET + 255) / 256;       // 3321
    const int gemmBlocks = (NN + 31) / 32;         // 1563
    const int attnBlocks = NN / 8;                 // 6250
    const int normBlocks = (NN * CC) / 256;        // 12500

    // fork: CSR build on s2, overlapped with layer-1 GEMM
    cudaEventRecord(evA, 0);
    cudaStreamWaitEvent(s2, evA, 0);
    cudaMemsetAsync(dDeg, 0, NN * sizeof(int), s2);
    k_histo<<<edgeBlocks, 256, 0, s2>>>(ei);
    k_scan<<<1, 1024, 0, s2>>>();
    k_scatter<<<edgeBlocks, 256, 0, s2>>>(ei);
    cudaEventRecord(evB, s2);

    cudaMemsetAsync(cs0,  0, 3 * CC * sizeof(float), 0);
    cudaMemsetAsync(css0, 0, 3 * CC * sizeof(float), 0);

    const float* xin = x;
    int din = 3;
    const float *pgw = nullptr, *pgb = nullptr, *pgm = nullptr;
    for (int l = 0; l < 3; l++) {
        int base = 2 + 7 * l;
        const float* Wl  = (const float*)d_in[base + 0];
        const float* Wr  = (const float*)d_in[base + 1];
        const float* att = (const float*)d_in[base + 2];
        const float* b   = (const float*)d_in[base + 3];

        float* csP  = cs0  + (l > 0 ? (l - 1) * CC : 0);
        float* cssP = css0 + (l > 0 ? (l - 1) * CC : 0);
        k_gemm<<<gemmBlocks, dim3(32, 4)>>>(xin, Wl, Wr, din,
                                            pgw, pgb, pgm, csP, cssP);
        if (l == 0) cudaStreamWaitEvent(0, evB, 0);
        k_attn<<<attnBlocks, 256>>>(att, b, cs0 + l * CC, css0 + l * CC);

        pgw = (const float*)d_in[base + 4];
        pgb = (const float*)d_in[base + 5];
        pgm = (const float*)d_in[base + 6];
        xin = nullptr;
        din = CC;
    }
    k_norm<<<normBlocks, 256>>>(pgw, pgb, pgm,
                                cs0 + 2 * CC, css0 + 2 * CC, out);
}